// round 16
// baseline (speedup 1.0000x reference)
#include <cuda_runtime.h>

#define BB 4
#define G 8
#define DD 8
#define HH 256
#define WW 320
#define NN 9
#define HW (HH*WW)

typedef unsigned long long ull;

__device__ float4 g_scratch[BB * HW * 4];

__device__ __forceinline__ ull pk(float lo, float hi) {
    ull r; asm("mov.b64 %0, {%1, %2};" : "=l"(r) : "f"(lo), "f"(hi)); return r;
}
__device__ __forceinline__ void upk(ull v, float& lo, float& hi) {
    asm("mov.b64 {%0, %1}, %2;" : "=f"(lo), "=f"(hi) : "l"(v));
}
__device__ __forceinline__ ull ffma2(ull a, ull b, ull c) {
    ull d; asm("fma.rn.f32x2 %0, %1, %2, %3;" : "=l"(d) : "l"(a), "l"(b), "l"(c)); return d;
}
__device__ __forceinline__ ull relu2(ull v) {
    float lo, hi; upk(v, lo, hi);
    return pk(fmaxf(lo, 0.f), fmaxf(hi, 0.f));
}

// One thread per (b,h,w). Packed f32x2 math: two adjacent depths share one FFMA2.
// Weights duplicated {w,w} in smem so an LDS.64 yields a packed multiplicand.
__global__ __launch_bounds__(256) void mlp_kernel(
    const float* __restrict__ cost, const float* __restrict__ ds,
    const float* __restrict__ dmin, const float* __restrict__ dmax,
    const float* __restrict__ w0, const float* __restrict__ g0,
    const float* __restrict__ b0, const float* __restrict__ m0,
    const float* __restrict__ v0, const float* __restrict__ w1,
    const float* __restrict__ g1, const float* __restrict__ b1,
    const float* __restrict__ m1, const float* __restrict__ v1,
    const float* __restrict__ w2, const float* __restrict__ b2)
{
    __shared__ __align__(16) float2 s_w0[128];  // [o*8+g], duplicated
    __shared__ __align__(16) float2 s_b0[16];
    __shared__ __align__(16) float2 s_w1[128];  // [o*16+c]
    __shared__ __align__(16) float2 s_b1[8];
    __shared__ __align__(16) float2 s_w2[8];
    __shared__ float2 s_b2;
    int t = threadIdx.x;
    if (t < 16) {
        float a = g0[t] * rsqrtf(v0[t] + 1e-5f);
        #pragma unroll
        for (int g = 0; g < 8; ++g) { float wv = w0[t * 8 + g] * a; s_w0[t * 8 + g] = make_float2(wv, wv); }
        float bv = b0[t] - m0[t] * a;
        s_b0[t] = make_float2(bv, bv);
    } else if (t >= 32 && t < 40) {
        int o = t - 32;
        float a = g1[o] * rsqrtf(v1[o] + 1e-5f);
        #pragma unroll
        for (int c = 0; c < 16; ++c) { float wv = w1[o * 16 + c] * a; s_w1[o * 16 + c] = make_float2(wv, wv); }
        float bv = b1[o] - m1[o] * a;
        s_b1[o] = make_float2(bv, bv);
        float w2v = w2[o];
        s_w2[o] = make_float2(w2v, w2v);
    } else if (t == 64) {
        float bv = b2[0];
        s_b2 = make_float2(bv, bv);
    }
    __syncthreads();

    const ull* w0u = (const ull*)s_w0;
    const ull* b0u = (const ull*)s_b0;
    const ull* w1u = (const ull*)s_w1;
    const ull* b1u = (const ull*)s_b1;
    const ull* w2u = (const ull*)s_w2;

    int tid = blockIdx.x * 256 + threadIdx.x;
    int b = tid / HW;
    int p = tid % HW;
    float inv_min = 1.f / __ldg(dmin + b);
    float inv_max = 1.f / __ldg(dmax + b);
    float inv_range = 1.f / (inv_min - inv_max);

    const float* costb = cost + (size_t)b * G * DD * HW + p;
    const float* dsb   = ds + (size_t)b * DD * HW + p;
    ull b2p = ((const ull*)&s_b2)[0];

    #pragma unroll
    for (int q = 0; q < 2; ++q) {       // 4 depths per quad: pairs (d0,d0+1),(d0+2,d0+3)
        int d0 = q * 4;
        ull x[8][2];
        #pragma unroll
        for (int g = 0; g < 8; ++g) {
            const float* cg = costb + (size_t)(g * DD + d0) * HW;
            float v0a = cg[0], v1a = cg[HW], v2a = cg[2 * HW], v3a = cg[3 * HW];
            x[g][0] = pk(v0a, v1a);
            x[g][1] = pk(v2a, v3a);
        }
        ull h0[16][2];
        #pragma unroll
        for (int o = 0; o < 16; ++o) {
            ull a0 = b0u[o], a1 = a0;
            #pragma unroll
            for (int g = 0; g < 8; ++g) {
                ull wv = w0u[o * 8 + g];
                a0 = ffma2(wv, x[g][0], a0);
                a1 = ffma2(wv, x[g][1], a1);
            }
            h0[o][0] = relu2(a0);
            h0[o][1] = relu2(a1);
        }
        ull sp0 = b2p, sp1 = b2p;
        #pragma unroll
        for (int o = 0; o < 8; ++o) {
            ull a0 = b1u[o], a1 = a0;
            #pragma unroll
            for (int c = 0; c < 16; ++c) {
                ull wv = w1u[o * 16 + c];
                a0 = ffma2(wv, h0[c][0], a0);
                a1 = ffma2(wv, h0[c][1], a1);
            }
            ull wv2 = w2u[o];
            sp0 = ffma2(wv2, relu2(a0), sp0);
            sp1 = ffma2(wv2, relu2(a1), sp1);
        }
        float sa0, sa1, sb0v, sb1v;
        upk(sp0, sa0, sa1);
        upk(sp1, sb0v, sb1v);

        float xn0 = (1.f / dsb[(size_t)(d0 + 0) * HW] - inv_max) * inv_range;
        float xn1 = (1.f / dsb[(size_t)(d0 + 1) * HW] - inv_max) * inv_range;
        float xn2 = (1.f / dsb[(size_t)(d0 + 2) * HW] - inv_max) * inv_range;
        float xn3 = (1.f / dsb[(size_t)(d0 + 3) * HW] - inv_max) * inv_range;
        g_scratch[(size_t)tid * 4 + 2 * q]     = make_float4(xn0, sa0, xn1, sa1);
        g_scratch[(size_t)tid * 4 + 2 * q + 1] = make_float4(xn2, sb0v, xn3, sb1v);
    }
}

// 4 threads per pixel: thread (pix, j) owns depth-pair {2j, 2j+1}.
// Two-phase: batch all grid/fwt loads up front, then corner gathers + math.
__global__ __launch_bounds__(256) void agg_kernel(const float* __restrict__ grid,
                                                  const float* __restrict__ fwt,
                                                  float* __restrict__ out) {
    int tid = blockIdx.x * 256 + threadIdx.x;
    int pix = tid >> 2;
    int j = tid & 3;
    int b = pix / HW;
    int p = pix % HW;
    int h = p / WW;
    int w = p % WW;

    // Phase 1: batch independent loads (grid coords + feature weights)
    float2 g2v[NN];
    float fv[NN];
    const float2* gbase = (const float2*)grid + (size_t)(b * NN * HH + h) * WW + w;
    const float* fbase = fwt + (size_t)(b * NN * HH + h) * WW + w;
    #pragma unroll
    for (int n = 0; n < NN; ++n) {
        g2v[n] = gbase[(size_t)n * HH * WW];
        fv[n]  = fbase[(size_t)n * HH * WW];
    }

    float4 c = g_scratch[(size_t)pix * 4 + j];
    float xn0 = c.x, xn1 = c.z;
    float acc0 = 0.f, acc1 = 0.f;

    const float4* base = g_scratch + (size_t)b * HW * 4 + j;
    const float LOG2E2 = 2.885390082f;   // 2*log2(e)
    const float BIAS   = -5.770780164f;  // -4*log2(e)

    // Phase 2: per-neighbor gather + accumulate
    #pragma unroll
    for (int n = 0; n < NN; ++n) {
        float fx = fminf(fmaxf((g2v[n].x + 1.f) * (0.5f * WW) - 0.5f, 0.f), (float)(WW - 1));
        float fy = fminf(fmaxf((g2v[n].y + 1.f) * (0.5f * HH) - 0.5f, 0.f), (float)(HH - 1));
        float x0f = floorf(fx), y0f = floorf(fy);
        float wx = fx - x0f, wy = fy - y0f;
        int x0 = (int)x0f, y0 = (int)y0f;
        int x1 = min(x0 + 1, WW - 1), y1 = min(y0 + 1, HH - 1);
        float w00 = (1.f - wx) * (1.f - wy);
        float w01 = wx * (1.f - wy);
        float w10 = (1.f - wx) * wy;
        float w11 = wx * wy;
        float f = fv[n];

        float4 a0 = base[(size_t)(y0 * WW + x0) * 4];
        float4 a1 = base[(size_t)(y0 * WW + x1) * 4];
        float4 a2 = base[(size_t)(y1 * WW + x0) * 4];
        float4 a3 = base[(size_t)(y1 * WW + x1) * 4];

        float xs0 = w00 * a0.x + w01 * a1.x + w10 * a2.x + w11 * a3.x;
        float ss0 = w00 * a0.y + w01 * a1.y + w10 * a2.y + w11 * a3.y;
        float xs1 = w00 * a0.z + w01 * a1.z + w10 * a2.z + w11 * a3.z;
        float ss1 = w00 * a0.w + w01 * a1.w + w10 * a2.w + w11 * a3.w;

        float diff0 = fminf(fabsf(xs0 - xn0) * 40.f, 4.f);
        float diff1 = fminf(fabsf(xs1 - xn1) * 40.f, 4.f);
        float dw0 = 1.f / (1.f + exp2f(fmaf(diff0, LOG2E2, BIAS)));
        float dw1 = 1.f / (1.f + exp2f(fmaf(diff1, LOG2E2, BIAS)));
        acc0 = fmaf(ss0 * f, dw0, acc0);
        acc1 = fmaf(ss1 * f, dw1, acc1);
    }

    out[(size_t)(b * DD + 2 * j) * HW + p]     = acc0;
    out[(size_t)(b * DD + 2 * j + 1) * HW + p] = acc1;
}

extern "C" void kernel_launch(void* const* d_in, const int* in_sizes, int n_in,
                              void* d_out, int out_size) {
    const float* cost = (const float*)d_in[0];
    const float* ds   = (const float*)d_in[1];
    const float* dmin = (const float*)d_in[2];
    const float* dmax = (const float*)d_in[3];
    const float* grid = (const float*)d_in[4];
    const float* fwt  = (const float*)d_in[5];

    int total = BB * HW;                    // 327680 pixels
    mlp_kernel<<<total / 256, 256>>>(cost, ds, dmin, dmax,
                                     (const float*)d_in[6], (const float*)d_in[7],
                                     (const float*)d_in[8], (const float*)d_in[9],
                                     (const float*)d_in[10], (const float*)d_in[11],
                                     (const float*)d_in[12], (const float*)d_in[13],
                                     (const float*)d_in[14], (const float*)d_in[15],
                                     (const float*)d_in[16], (const float*)d_in[17]);
    agg_kernel<<<total * 4 / 256, 256>>>(grid, fwt, (float*)d_out);
}